// round 1
// baseline (speedup 1.0000x reference)
#include <cuda_runtime.h>
#include <math.h>

// Problem constants (fixed by the reference: B=8, CK=64, H=W=64)
#define BATCH 8
#define CKDIM 64
#define HW    4096
#define TM    128
#define TN    128
#define KCHUNK 32

// Per-(b,n) column sums of exp(affinity). 32K floats, static device scratch.
__device__ float g_sums[BATCH * HW];

__global__ void zero_sums_kernel() {
    int i = blockIdx.x * blockDim.x + threadIdx.x;
    if (i < BATCH * HW) g_sums[i] = 0.0f;
}

__global__ void recip_sums_kernel() {
    int i = blockIdx.x * blockDim.x + threadIdx.x;
    if (i < BATCH * HW) g_sums[i] = 1.0f / g_sums[i];
}

// Fused: E[b,m,n] = exp( (1/8) * sum_c Mk[b,c,m] * Qk[b,c,n] ), written to out,
// plus column sums accumulated into g_sums[b*HW + n].
// Tile: 128(m) x 128(n) x 64(c), K processed in 2 chunks of 32 to keep smem small.
__global__ __launch_bounds__(256, 2)
void gemm_exp_kernel(const float* __restrict__ Mk,
                     const float* __restrict__ Qk,
                     float* __restrict__ out) {
    // 32 KB shared: As (Mk chunk, [c][m]) + Bs (Qk chunk scaled, [c][n]).
    // After the GEMM, the first 8 KB are reused for the column-sum reduction.
    __shared__ float smem[2 * KCHUNK * TN];
    float (*As)[TN] = (float(*)[TN])smem;                 // [KCHUNK][128]
    float (*Bs)[TN] = (float(*)[TN])(smem + KCHUNK * TN); // [KCHUNK][128]

    const int b  = blockIdx.z;
    const int m0 = blockIdx.y * TM;
    const int n0 = blockIdx.x * TN;
    const int tid = threadIdx.x;
    const int tx = tid & 15;   // n sub-tile (8 cols)
    const int ty = tid >> 4;   // m sub-tile (8 rows)

    const float* Mb = Mk + (size_t)b * CKDIM * HW;
    const float* Qb = Qk + (size_t)b * CKDIM * HW;

    float acc[8][8];
#pragma unroll
    for (int i = 0; i < 8; i++)
#pragma unroll
        for (int j = 0; j < 8; j++) acc[i][j] = 0.0f;

    for (int c0 = 0; c0 < CKDIM; c0 += KCHUNK) {
        __syncthreads();  // protect smem reuse from previous chunk's reads
        // Load chunk: 32 rows x 128 floats per array = 1024 float4 each.
        for (int i = tid; i < KCHUNK * TN / 4; i += 256) {
            int c  = i >> 5;          // 0..31
            int mm = (i & 31) << 2;   // 0..124 step 4
            float4 v = *(const float4*)(Mb + (size_t)(c0 + c) * HW + m0 + mm);
            *(float4*)&As[c][mm] = v;
            float4 w = *(const float4*)(Qb + (size_t)(c0 + c) * HW + n0 + mm);
            w.x *= 0.125f; w.y *= 0.125f; w.z *= 0.125f; w.w *= 0.125f;
            *(float4*)&Bs[c][mm] = w;
        }
        __syncthreads();

#pragma unroll 4
        for (int c = 0; c < KCHUNK; c++) {
            float a[8], bb[8];
            *(float4*)&a[0]  = *(const float4*)&As[c][ty * 8];
            *(float4*)&a[4]  = *(const float4*)&As[c][ty * 8 + 4];
            *(float4*)&bb[0] = *(const float4*)&Bs[c][tx * 8];
            *(float4*)&bb[4] = *(const float4*)&Bs[c][tx * 8 + 4];
#pragma unroll
            for (int i = 0; i < 8; i++)
#pragma unroll
                for (int j = 0; j < 8; j++)
                    acc[i][j] = fmaf(a[i], bb[j], acc[i][j]);
        }
    }
    __syncthreads();  // smem reads done; safe to reuse for reduction

    // Epilogue: exp, store, per-thread column partial sums.
    float colsum[8];
#pragma unroll
    for (int j = 0; j < 8; j++) colsum[j] = 0.0f;

#pragma unroll
    for (int i = 0; i < 8; i++) {
        float e[8];
#pragma unroll
        for (int j = 0; j < 8; j++) {
            e[j] = __expf(acc[i][j]);
            colsum[j] += e[j];
        }
        float* rowp = out + ((size_t)(b * HW + m0 + ty * 8 + i)) * HW + n0 + tx * 8;
        *(float4*)(rowp)     = make_float4(e[0], e[1], e[2], e[3]);
        *(float4*)(rowp + 4) = make_float4(e[4], e[5], e[6], e[7]);
    }

    // CTA-level column reduction: Sred[16][128] aliases As (8 KB).
    float (*Sred)[TN] = (float(*)[TN])smem;
#pragma unroll
    for (int j = 0; j < 8; j++) Sred[ty][tx * 8 + j] = colsum[j];
    __syncthreads();
    if (tid < TN) {
        float s = 0.0f;
#pragma unroll
        for (int r = 0; r < 16; r++) s += Sred[r][tid];
        atomicAdd(&g_sums[b * HW + n0 + tid], s);
    }
}

// out[b,m,n] *= rsum[b,n]  (g_sums holds reciprocals at this point)
__global__ __launch_bounds__(256)
void normalize_kernel(float* __restrict__ out) {
    size_t idx = (size_t)blockIdx.x * blockDim.x + threadIdx.x;
    size_t i4 = idx * 4;                 // element offset, 4 per thread
    int n = (int)(i4 & (HW - 1));        // column (contiguous)
    size_t bm = i4 >> 12;                // b*HW + m
    int b = (int)(bm >> 12);

    float4 v = *(float4*)(out + i4);
    const float4 s = *(const float4*)(g_sums + b * HW + n);
    v.x *= s.x; v.y *= s.y; v.z *= s.z; v.w *= s.w;
    *(float4*)(out + i4) = v;
}

extern "C" void kernel_launch(void* const* d_in, const int* in_sizes, int n_in,
                              void* d_out, int out_size) {
    const float* Mk = (const float*)d_in[0];
    const float* Qk = (const float*)d_in[1];
    float* out = (float*)d_out;

    zero_sums_kernel<<<(BATCH * HW + 255) / 256, 256>>>();

    dim3 grid(HW / TN, HW / TM, BATCH);   // (32, 32, 8)
    gemm_exp_kernel<<<grid, 256>>>(Mk, Qk, out);

    recip_sums_kernel<<<(BATCH * HW + 255) / 256, 256>>>();

    size_t total4 = (size_t)BATCH * HW * HW / 4;   // 33,554,432 float4 threads
    normalize_kernel<<<(unsigned)(total4 / 256), 256>>>(out);
}

// round 3
// speedup vs baseline: 1.4817x; 1.4817x over previous
#include <cuda_runtime.h>
#include <stdint.h>

// Problem constants: B=8, CK=64, H=W=64 -> HW=4096
#define BATCH 8
#define CKDIM 64
#define HW    4096

// Dynamic SMEM layout: four 128x64 bf16 K-major SW128 tiles + reduction buf
#define AH_OFF 0        // Mk hi
#define AL_OFF 16384    // Mk lo
#define BH_OFF 32768    // Qk hi (scaled by 1/8)
#define BL_OFF 49152    // Qk lo
#define RED_OFF 65536   // 128 floats column-sum reduce
#define SMEM_BYTES (65536 + 512)

__device__ float g_sums[BATCH * HW];

__global__ void zero_sums_kernel() {
    int i = blockIdx.x * blockDim.x + threadIdx.x;
    if (i < BATCH * HW) g_sums[i] = 0.0f;
}
__global__ void recip_sums_kernel() {
    int i = blockIdx.x * blockDim.x + threadIdx.x;
    if (i < BATCH * HW) g_sums[i] = 1.0f / g_sums[i];
}

__device__ __forceinline__ uint32_t smem_u32(const void* p) {
    uint32_t a;
    asm("{ .reg .u64 t; cvta.to.shared.u64 t, %1; cvt.u32.u64 %0, t; }"
        : "=r"(a) : "l"(p));
    return a;
}
__device__ __forceinline__ uint32_t swz(uint32_t off) {
    return off ^ ((off >> 3) & 0x70);
}
// Split two fp32 into bf16x2 hi word + bf16x2 residual word. hi = {lo16:v0, hi16:v1}
__device__ __forceinline__ void split2(float v0, float v1, uint32_t& hi, uint32_t& lo) {
    asm("cvt.rn.satfinite.bf16x2.f32 %0, %1, %2;" : "=r"(hi) : "f"(v1), "f"(v0));
    float h0 = __uint_as_float(hi << 16);
    float h1 = __uint_as_float(hi & 0xFFFF0000u);
    float l0 = v0 - h0;
    float l1 = v1 - h1;
    asm("cvt.rn.satfinite.bf16x2.f32 %0, %1, %2;" : "=r"(lo) : "f"(l1), "f"(l0));
}
__device__ __forceinline__ void sts32(uint32_t addr, uint32_t v) {
    asm volatile("st.shared.b32 [%0], %1;" :: "r"(addr), "r"(v));
}
__device__ __forceinline__ void ldsm4(uint32_t addr, uint32_t* r) {
    asm volatile("ldmatrix.sync.aligned.m8n8.x4.shared.b16 {%0,%1,%2,%3}, [%4];"
                 : "=r"(r[0]), "=r"(r[1]), "=r"(r[2]), "=r"(r[3]) : "r"(addr));
}
__device__ __forceinline__ void mma16816(float* d, const uint32_t* a, const uint32_t* b) {
    asm volatile(
        "mma.sync.aligned.m16n8k16.row.col.f32.bf16.bf16.f32 "
        "{%0,%1,%2,%3}, {%4,%5,%6,%7}, {%8,%9}, {%0,%1,%2,%3};"
        : "+f"(d[0]), "+f"(d[1]), "+f"(d[2]), "+f"(d[3])
        : "r"(a[0]), "r"(a[1]), "r"(a[2]), "r"(a[3]), "r"(b[0]), "r"(b[1]));
}

// Fused: E[m,n] = exp( sum_c Mk[b,c,m] * Qk[b,c,n]/8 ) -> out[b,m,n],
// column sums (over m) accumulated into g_sums[b*HW + n].
__global__ __launch_bounds__(256, 2)
void gemm_exp_mma(const float* __restrict__ Mk, const float* __restrict__ Qk,
                  float* __restrict__ out) {
    extern __shared__ char smem[];
    const uint32_t sb = smem_u32(smem);
    const int tid = threadIdx.x, lane = tid & 31, wid = tid >> 5;
    const int wm = wid >> 1, wn = wid & 1;           // 4x2 warp grid
    const int b = blockIdx.z;
    const int m0 = blockIdx.y * 128, n0 = blockIdx.x * 128;

    const float* Ap = Mk + (size_t)b * CKDIM * HW + m0;
    const float* Bp = Qk + (size_t)b * CKDIM * HW + n0;

    if (tid < 128) ((float*)(smem + RED_OFF))[tid] = 0.0f;

    // ---- load + fp32->bf16 hi/lo split, K-major SW128 rows (128B each) ----
    // Mapping per u: 16-lane row groups x 2 k-pairs per warp -> coalesced LDG
    // (128B) and 4-way-max STS conflicts.
#pragma unroll
    for (int it = 0; it < 8; it++) {
        int u  = tid + it * 256;                       // 0..2047
        int r  = ((u & 15) + (u >> 9) * 16) * 2;       // even row 0..126
        int cp = ((u >> 4) & 1) + ((u >> 5) & 15) * 2; // k-pair 0..31
        // A (Mk)
        float2 x0 = *(const float2*)(Ap + (size_t)(2 * cp)     * HW + r);
        float2 x1 = *(const float2*)(Ap + (size_t)(2 * cp + 1) * HW + r);
        uint32_t hi, lo;
        uint32_t o0 = swz((uint32_t)(r * 128 + cp * 4));
        uint32_t o1 = swz((uint32_t)((r + 1) * 128 + cp * 4));
        split2(x0.x, x1.x, hi, lo);
        sts32(sb + AH_OFF + o0, hi); sts32(sb + AL_OFF + o0, lo);
        split2(x0.y, x1.y, hi, lo);
        sts32(sb + AH_OFF + o1, hi); sts32(sb + AL_OFF + o1, lo);
        // B (Qk / 8)
        float2 y0 = *(const float2*)(Bp + (size_t)(2 * cp)     * HW + r);
        float2 y1 = *(const float2*)(Bp + (size_t)(2 * cp + 1) * HW + r);
        split2(y0.x * 0.125f, y1.x * 0.125f, hi, lo);
        sts32(sb + BH_OFF + o0, hi); sts32(sb + BL_OFF + o0, lo);
        split2(y0.y * 0.125f, y1.y * 0.125f, hi, lo);
        sts32(sb + BH_OFF + o1, hi); sts32(sb + BL_OFF + o1, lo);
    }
    __syncthreads();

    // ---- MMA mainloop: 4 k-steps x 3 terms (AhBh + AlBh + AhBl) ----
    float acc[2][8][4];
#pragma unroll
    for (int i = 0; i < 2; i++)
#pragma unroll
        for (int j = 0; j < 8; j++)
#pragma unroll
            for (int q = 0; q < 4; q++) acc[i][j][q] = 0.0f;

    // per-lane ldmatrix address components
    const int a_row = wm * 32 + (lane & 7) + ((lane >> 3) & 1) * 8;
    const int a_kb  = (lane >> 4) * 16;
    const int b_row = wn * 64 + (lane & 7) + (lane >> 4) * 8;  // group>>1 selects ntile parity
    const int b_kb  = ((lane >> 3) & 1) * 16;

#pragma unroll
    for (int ks = 0; ks < 4; ks++) {
        const int kbase = ks * 32;
        uint32_t ah[2][4], al[2][4], bf[16];
#pragma unroll
        for (int mi = 0; mi < 2; mi++)
            ldsm4(sb + AH_OFF + swz((uint32_t)((a_row + mi * 16) * 128 + kbase + a_kb)), ah[mi]);
#pragma unroll
        for (int jp = 0; jp < 4; jp++)
            ldsm4(sb + BH_OFF + swz((uint32_t)((b_row + jp * 16) * 128 + kbase + b_kb)), &bf[jp * 4]);
#pragma unroll
        for (int mi = 0; mi < 2; mi++)
#pragma unroll
            for (int ni = 0; ni < 8; ni++)
                mma16816(acc[mi][ni], ah[mi], &bf[ni * 2]);
#pragma unroll
        for (int mi = 0; mi < 2; mi++)
            ldsm4(sb + AL_OFF + swz((uint32_t)((a_row + mi * 16) * 128 + kbase + a_kb)), al[mi]);
#pragma unroll
        for (int mi = 0; mi < 2; mi++)
#pragma unroll
            for (int ni = 0; ni < 8; ni++)
                mma16816(acc[mi][ni], al[mi], &bf[ni * 2]);
#pragma unroll
        for (int jp = 0; jp < 4; jp++)
            ldsm4(sb + BL_OFF + swz((uint32_t)((b_row + jp * 16) * 128 + kbase + b_kb)), &bf[jp * 4]);
#pragma unroll
        for (int mi = 0; mi < 2; mi++)
#pragma unroll
            for (int ni = 0; ni < 8; ni++)
                mma16816(acc[mi][ni], ah[mi], &bf[ni * 2]);
    }

    // ---- epilogue: exp, store, column sums ----
    float cs[16];
#pragma unroll
    for (int q = 0; q < 16; q++) cs[q] = 0.0f;

    const int mrow = m0 + wm * 32 + (lane >> 2);
    const int ncol = n0 + wn * 64 + 2 * (lane & 3);
#pragma unroll
    for (int mi = 0; mi < 2; mi++) {
#pragma unroll
        for (int ni = 0; ni < 8; ni++) {
            float e0 = __expf(acc[mi][ni][0]);
            float e1 = __expf(acc[mi][ni][1]);
            float e2 = __expf(acc[mi][ni][2]);
            float e3 = __expf(acc[mi][ni][3]);
            size_t ro = (size_t)(b * HW + mrow + mi * 16) * HW + ncol + ni * 8;
            *(float2*)(out + ro)                  = make_float2(e0, e1);
            *(float2*)(out + ro + (size_t)8 * HW) = make_float2(e2, e3);
            cs[2 * ni]     += e0 + e2;
            cs[2 * ni + 1] += e1 + e3;
        }
    }
    // butterfly over lanes sharing (lane & 3): masks 4, 8, 16
#pragma unroll
    for (int msk = 4; msk < 32; msk <<= 1)
#pragma unroll
        for (int q = 0; q < 16; q++)
            cs[q] += __shfl_xor_sync(0xFFFFFFFFu, cs[q], msk);

    if (lane < 4) {
        float* red = (float*)(smem + RED_OFF);
#pragma unroll
        for (int ni = 0; ni < 8; ni++) {
            atomicAdd(&red[wn * 64 + ni * 8 + 2 * lane],     cs[2 * ni]);
            atomicAdd(&red[wn * 64 + ni * 8 + 2 * lane + 1], cs[2 * ni + 1]);
        }
    }
    __syncthreads();
    if (tid < 128)
        atomicAdd(&g_sums[b * HW + n0 + tid], ((float*)(smem + RED_OFF))[tid]);
}

// out[b,m,n] *= rsum[b,n]  (g_sums holds reciprocals)
__global__ __launch_bounds__(256)
void normalize_kernel(float* __restrict__ out) {
    size_t idx = (size_t)blockIdx.x * blockDim.x + threadIdx.x;
    size_t i4  = idx * 4;
    int n = (int)(i4 & (HW - 1));
    size_t bm = i4 >> 12;
    int b = (int)(bm >> 12);
    float4 v = *(float4*)(out + i4);
    const float4 s = *(const float4*)(g_sums + b * HW + n);
    v.x *= s.x; v.y *= s.y; v.z *= s.z; v.w *= s.w;
    *(float4*)(out + i4) = v;
}

extern "C" void kernel_launch(void* const* d_in, const int* in_sizes, int n_in,
                              void* d_out, int out_size) {
    const float* Mk = (const float*)d_in[0];
    const float* Qk = (const float*)d_in[1];
    float* out = (float*)d_out;

    cudaFuncSetAttribute(gemm_exp_mma, cudaFuncAttributeMaxDynamicSharedMemorySize,
                         SMEM_BYTES);

    zero_sums_kernel<<<(BATCH * HW + 255) / 256, 256>>>();

    dim3 grid(HW / 128, HW / 128, BATCH);   // (32, 32, 8)
    gemm_exp_mma<<<grid, 256, SMEM_BYTES>>>(Mk, Qk, out);

    recip_sums_kernel<<<(BATCH * HW + 255) / 256, 256>>>();

    size_t total4 = (size_t)BATCH * HW * HW / 4;
    normalize_kernel<<<(unsigned)(total4 / 256), 256>>>(out);
}

// round 4
// speedup vs baseline: 1.6578x; 1.1189x over previous
#include <cuda_runtime.h>
#include <cuda_fp16.h>
#include <stdint.h>

// Problem constants: B=8, CK=64, H=W=64 -> HW=4096
#define BATCH 8
#define CKDIM 64
#define HW    4096

// Dynamic SMEM: three 128x64 fp16 K-major SW128 tiles + reduction buf
#define AH_OFF 0        // Mk hi (fp16)
#define AL_OFF 16384    // Mk lo (fp16 residual)
#define BH_OFF 32768    // Qk/8 (fp16, single)
#define RED_OFF 49152   // 128 floats column-sum reduce
#define SMEM_BYTES (49152 + 512)

__device__ float g_sums[BATCH * HW];

__global__ void zero_sums_kernel() {
    int i = blockIdx.x * blockDim.x + threadIdx.x;
    if (i < BATCH * HW) g_sums[i] = 0.0f;
}
__global__ void recip_sums_kernel() {
    int i = blockIdx.x * blockDim.x + threadIdx.x;
    if (i < BATCH * HW) g_sums[i] = 1.0f / g_sums[i];
}

__device__ __forceinline__ uint32_t smem_u32(const void* p) {
    uint32_t a;
    asm("{ .reg .u64 t; cvta.to.shared.u64 t, %1; cvt.u32.u64 %0, t; }"
        : "=r"(a) : "l"(p));
    return a;
}
__device__ __forceinline__ uint32_t swz(uint32_t off) {
    return off ^ ((off >> 3) & 0x70);
}
// fp16 hi/lo split of two fp32 values: hi word = {lo16: h(v0), hi16: h(v1)},
// lo word = fp16 residuals.
__device__ __forceinline__ void split2h(float v0, float v1, uint32_t& hi, uint32_t& lo) {
    __half2 h = __floats2half2_rn(v0, v1);
    float2 hf = __half22float2(h);
    __half2 l = __floats2half2_rn(v0 - hf.x, v1 - hf.y);
    hi = *(uint32_t*)&h;
    lo = *(uint32_t*)&l;
}
__device__ __forceinline__ uint32_t pack2h(float v0, float v1) {
    __half2 h = __floats2half2_rn(v0, v1);
    return *(uint32_t*)&h;
}
__device__ __forceinline__ void sts32(uint32_t addr, uint32_t v) {
    asm volatile("st.shared.b32 [%0], %1;" :: "r"(addr), "r"(v));
}
__device__ __forceinline__ void ldsm4(uint32_t addr, uint32_t* r) {
    asm volatile("ldmatrix.sync.aligned.m8n8.x4.shared.b16 {%0,%1,%2,%3}, [%4];"
                 : "=r"(r[0]), "=r"(r[1]), "=r"(r[2]), "=r"(r[3]) : "r"(addr));
}
__device__ __forceinline__ void mma16816(float* d, const uint32_t* a, const uint32_t* b) {
    asm volatile(
        "mma.sync.aligned.m16n8k16.row.col.f32.f16.f16.f32 "
        "{%0,%1,%2,%3}, {%4,%5,%6,%7}, {%8,%9}, {%0,%1,%2,%3};"
        : "+f"(d[0]), "+f"(d[1]), "+f"(d[2]), "+f"(d[3])
        : "r"(a[0]), "r"(a[1]), "r"(a[2]), "r"(a[3]), "r"(b[0]), "r"(b[1]));
}

// Fused: E[m,n] = exp( sum_c Mk[b,c,m] * Qk[b,c,n]/8 ) -> out[b,m,n],
// column sums (over m) accumulated into g_sums[b*HW + n].
// A = Mk split into fp16 hi+lo; B = Qk/8 rounded once to fp16.
// (Ah+Al)*Bh == A*Bh exactly, so only B's 2^-12 rounding survives -> ~2e-4.
__global__ __launch_bounds__(256, 2)
void gemm_exp_mma(const float* __restrict__ Mk, const float* __restrict__ Qk,
                  float* __restrict__ out) {
    extern __shared__ char smem[];
    const uint32_t sb = smem_u32(smem);
    const int tid = threadIdx.x, lane = tid & 31, wid = tid >> 5;
    const int wm = wid >> 1, wn = wid & 1;           // 4x2 warp grid
    const int b = blockIdx.z;
    const int m0 = blockIdx.y * 128, n0 = blockIdx.x * 128;

    const float* Ap = Mk + (size_t)b * CKDIM * HW + m0;
    const float* Bp = Qk + (size_t)b * CKDIM * HW + n0;

    if (tid < 128) ((float*)(smem + RED_OFF))[tid] = 0.0f;

    // ---- load + convert, K-major SW128 rows (128B each) ----
#pragma unroll
    for (int it = 0; it < 8; it++) {
        int u  = tid + it * 256;                       // 0..2047
        int r  = ((u & 15) + (u >> 9) * 16) * 2;       // even row 0..126
        int cp = ((u >> 4) & 1) + ((u >> 5) & 15) * 2; // k-pair 0..31
        uint32_t o0 = swz((uint32_t)(r * 128 + cp * 4));
        uint32_t o1 = swz((uint32_t)((r + 1) * 128 + cp * 4));
        // A (Mk): hi/lo split
        float2 x0 = *(const float2*)(Ap + (size_t)(2 * cp)     * HW + r);
        float2 x1 = *(const float2*)(Ap + (size_t)(2 * cp + 1) * HW + r);
        uint32_t hi, lo;
        split2h(x0.x, x1.x, hi, lo);
        sts32(sb + AH_OFF + o0, hi); sts32(sb + AL_OFF + o0, lo);
        split2h(x0.y, x1.y, hi, lo);
        sts32(sb + AH_OFF + o1, hi); sts32(sb + AL_OFF + o1, lo);
        // B (Qk / 8): single fp16
        float2 y0 = *(const float2*)(Bp + (size_t)(2 * cp)     * HW + r);
        float2 y1 = *(const float2*)(Bp + (size_t)(2 * cp + 1) * HW + r);
        sts32(sb + BH_OFF + o0, pack2h(y0.x * 0.125f, y1.x * 0.125f));
        sts32(sb + BH_OFF + o1, pack2h(y0.y * 0.125f, y1.y * 0.125f));
    }
    __syncthreads();

    // ---- MMA mainloop: 4 k-steps x 2 terms (Ah*B + Al*B) ----
    float acc[2][8][4];
#pragma unroll
    for (int i = 0; i < 2; i++)
#pragma unroll
        for (int j = 0; j < 8; j++)
#pragma unroll
            for (int q = 0; q < 4; q++) acc[i][j][q] = 0.0f;

    const int a_row = wm * 32 + (lane & 7) + ((lane >> 3) & 1) * 8;
    const int a_kb  = (lane >> 4) * 16;
    const int b_row = wn * 64 + (lane & 7) + (lane >> 4) * 8;
    const int b_kb  = ((lane >> 3) & 1) * 16;

#pragma unroll
    for (int ks = 0; ks < 4; ks++) {
        const int kbase = ks * 32;
        uint32_t ah[2][4], al[2][4], bf[16];
#pragma unroll
        for (int mi = 0; mi < 2; mi++)
            ldsm4(sb + AH_OFF + swz((uint32_t)((a_row + mi * 16) * 128 + kbase + a_kb)), ah[mi]);
#pragma unroll
        for (int jp = 0; jp < 4; jp++)
            ldsm4(sb + BH_OFF + swz((uint32_t)((b_row + jp * 16) * 128 + kbase + b_kb)), &bf[jp * 4]);
#pragma unroll
        for (int mi = 0; mi < 2; mi++)
            ldsm4(sb + AL_OFF + swz((uint32_t)((a_row + mi * 16) * 128 + kbase + a_kb)), al[mi]);
#pragma unroll
        for (int mi = 0; mi < 2; mi++)
#pragma unroll
            for (int ni = 0; ni < 8; ni++)
                mma16816(acc[mi][ni], ah[mi], &bf[ni * 2]);
#pragma unroll
        for (int mi = 0; mi < 2; mi++)
#pragma unroll
            for (int ni = 0; ni < 8; ni++)
                mma16816(acc[mi][ni], al[mi], &bf[ni * 2]);
    }

    // ---- epilogue: exp, store, column sums ----
    float cs[16];
#pragma unroll
    for (int q = 0; q < 16; q++) cs[q] = 0.0f;

    const int mrow = m0 + wm * 32 + (lane >> 2);
    const int ncol = n0 + wn * 64 + 2 * (lane & 3);
#pragma unroll
    for (int mi = 0; mi < 2; mi++) {
#pragma unroll
        for (int ni = 0; ni < 8; ni++) {
            float e0 = __expf(acc[mi][ni][0]);
            float e1 = __expf(acc[mi][ni][1]);
            float e2 = __expf(acc[mi][ni][2]);
            float e3 = __expf(acc[mi][ni][3]);
            size_t ro = (size_t)(b * HW + mrow + mi * 16) * HW + ncol + ni * 8;
            *(float2*)(out + ro)                  = make_float2(e0, e1);
            *(float2*)(out + ro + (size_t)8 * HW) = make_float2(e2, e3);
            cs[2 * ni]     += e0 + e2;
            cs[2 * ni + 1] += e1 + e3;
        }
    }
#pragma unroll
    for (int msk = 4; msk < 32; msk <<= 1)
#pragma unroll
        for (int q = 0; q < 16; q++)
            cs[q] += __shfl_xor_sync(0xFFFFFFFFu, cs[q], msk);

    if (lane < 4) {
        float* red = (float*)(smem + RED_OFF);
#pragma unroll
        for (int ni = 0; ni < 8; ni++) {
            atomicAdd(&red[wn * 64 + ni * 8 + 2 * lane],     cs[2 * ni]);
            atomicAdd(&red[wn * 64 + ni * 8 + 2 * lane + 1], cs[2 * ni + 1]);
        }
    }
    __syncthreads();
    if (tid < 128)
        atomicAdd(&g_sums[b * HW + n0 + tid], ((float*)(smem + RED_OFF))[tid]);
}

// out[b,m,n] *= rsum[b,n]  (g_sums holds reciprocals)
__global__ __launch_bounds__(256)
void normalize_kernel(float* __restrict__ out) {
    size_t idx = (size_t)blockIdx.x * blockDim.x + threadIdx.x;
    size_t i4  = idx * 4;
    int n = (int)(i4 & (HW - 1));
    size_t bm = i4 >> 12;
    int b = (int)(bm >> 12);
    float4 v = *(float4*)(out + i4);
    const float4 s = *(const float4*)(g_sums + b * HW + n);
    v.x *= s.x; v.y *= s.y; v.z *= s.z; v.w *= s.w;
    *(float4*)(out + i4) = v;
}

extern "C" void kernel_launch(void* const* d_in, const int* in_sizes, int n_in,
                              void* d_out, int out_size) {
    const float* Mk = (const float*)d_in[0];
    const float* Qk = (const float*)d_in[1];
    float* out = (float*)d_out;

    cudaFuncSetAttribute(gemm_exp_mma, cudaFuncAttributeMaxDynamicSharedMemorySize,
                         SMEM_BYTES);

    zero_sums_kernel<<<(BATCH * HW + 255) / 256, 256>>>();

    dim3 grid(HW / 128, HW / 128, BATCH);   // (32, 32, 8)
    gemm_exp_mma<<<grid, 256, SMEM_BYTES>>>(Mk, Qk, out);

    recip_sums_kernel<<<(BATCH * HW + 255) / 256, 256>>>();

    size_t total4 = (size_t)BATCH * HW * HW / 4;
    normalize_kernel<<<(unsigned)(total4 / 256), 256>>>(out);
}

// round 5
// speedup vs baseline: 2.0291x; 1.2239x over previous
#include <cuda_runtime.h>
#include <cuda_fp16.h>
#include <stdint.h>

// Problem constants: B=8, CK=64, H=W=64 -> HW=4096
#define BATCH 8
#define CKDIM 64
#define HW    4096
#define NGROUPS 256           // (b, n_tile) column groups: 8 * 32
#define GROUP_CTAS 32         // m-tiles per group

// Dynamic SMEM: three 128x64 fp16 K-major SW128 tiles + reduction buf + ticket
#define AH_OFF 0        // Mk hi (fp16)
#define AL_OFF 16384    // Mk lo (fp16 residual)
#define BH_OFF 32768    // Qk/8 (fp16, single)
#define RED_OFF 49152   // 128 floats column-sum reduce
#define TKT_OFF (49152 + 512)
#define SMEM_BYTES (49152 + 512 + 16)

__device__ float g_sums[BATCH * HW];
__device__ unsigned g_cnt[NGROUPS];
__device__ unsigned g_ticket;

__global__ void init_kernel() {
    int i = blockIdx.x * blockDim.x + threadIdx.x;
    if (i < BATCH * HW) g_sums[i] = 0.0f;
    if (i < NGROUPS) g_cnt[i] = 0u;
    if (i == 0) g_ticket = 0u;
}

__device__ __forceinline__ uint32_t smem_u32(const void* p) {
    uint32_t a;
    asm("{ .reg .u64 t; cvta.to.shared.u64 t, %1; cvt.u32.u64 %0, t; }"
        : "=r"(a) : "l"(p));
    return a;
}
__device__ __forceinline__ uint32_t swz(uint32_t off) {
    return off ^ ((off >> 3) & 0x70);
}
__device__ __forceinline__ void split2h(float v0, float v1, uint32_t& hi, uint32_t& lo) {
    __half2 h = __floats2half2_rn(v0, v1);
    float2 hf = __half22float2(h);
    __half2 l = __floats2half2_rn(v0 - hf.x, v1 - hf.y);
    hi = *(uint32_t*)&h;
    lo = *(uint32_t*)&l;
}
__device__ __forceinline__ uint32_t pack2h(float v0, float v1) {
    __half2 h = __floats2half2_rn(v0, v1);
    return *(uint32_t*)&h;
}
__device__ __forceinline__ void sts32(uint32_t addr, uint32_t v) {
    asm volatile("st.shared.b32 [%0], %1;" :: "r"(addr), "r"(v));
}
__device__ __forceinline__ void ldsm4(uint32_t addr, uint32_t* r) {
    asm volatile("ldmatrix.sync.aligned.m8n8.x4.shared.b16 {%0,%1,%2,%3}, [%4];"
                 : "=r"(r[0]), "=r"(r[1]), "=r"(r[2]), "=r"(r[3]) : "r"(addr));
}
__device__ __forceinline__ void mma16816(float* d, const uint32_t* a, const uint32_t* b) {
    asm volatile(
        "mma.sync.aligned.m16n8k16.row.col.f32.f16.f16.f32 "
        "{%0,%1,%2,%3}, {%4,%5,%6,%7}, {%8,%9}, {%0,%1,%2,%3};"
        : "+f"(d[0]), "+f"(d[1]), "+f"(d[2]), "+f"(d[3])
        : "r"(a[0]), "r"(a[1]), "r"(a[2]), "r"(a[3]), "r"(b[0]), "r"(b[1]));
}

// Single fused kernel: GEMM (fp16 hi/lo split) + exp + cross-CTA column-sum
// exchange + in-register normalize + single store of the final softmax.
__global__ __launch_bounds__(256, 2)
void gemm_softmax_fused(const float* __restrict__ Mk, const float* __restrict__ Qk,
                        float* __restrict__ out) {
    extern __shared__ char smem[];
    const uint32_t sb = smem_u32(smem);
    const int tid = threadIdx.x, lane = tid & 31, wid = tid >> 5;
    const int wm = wid >> 1, wn = wid & 1;           // 4x2 warp grid

    // --- ticket-based tile assignment: group = 32 consecutive tickets ---
    if (tid == 0)
        *(unsigned*)(smem + TKT_OFF) = atomicAdd(&g_ticket, 1u);
    if (tid < 128) ((float*)(smem + RED_OFF))[tid] = 0.0f;
    __syncthreads();
    const unsigned tkt = *(const unsigned*)(smem + TKT_OFF);
    const int m_tile = (int)(tkt & 31u);
    const unsigned grp = tkt >> 5;                   // 0..255
    const int n_tile = (int)(grp & 31u);
    const int b      = (int)(grp >> 5);
    const int m0 = m_tile * 128, n0 = n_tile * 128;

    const float* Ap = Mk + (size_t)b * CKDIM * HW + m0;
    const float* Bp = Qk + (size_t)b * CKDIM * HW + n0;

    // ---- load + convert, K-major SW128 rows ----
#pragma unroll
    for (int it = 0; it < 8; it++) {
        int u  = tid + it * 256;
        int r  = ((u & 15) + (u >> 9) * 16) * 2;
        int cp = ((u >> 4) & 1) + ((u >> 5) & 15) * 2;
        uint32_t o0 = swz((uint32_t)(r * 128 + cp * 4));
        uint32_t o1 = swz((uint32_t)((r + 1) * 128 + cp * 4));
        float2 x0 = *(const float2*)(Ap + (size_t)(2 * cp)     * HW + r);
        float2 x1 = *(const float2*)(Ap + (size_t)(2 * cp + 1) * HW + r);
        uint32_t hi, lo;
        split2h(x0.x, x1.x, hi, lo);
        sts32(sb + AH_OFF + o0, hi); sts32(sb + AL_OFF + o0, lo);
        split2h(x0.y, x1.y, hi, lo);
        sts32(sb + AH_OFF + o1, hi); sts32(sb + AL_OFF + o1, lo);
        float2 y0 = *(const float2*)(Bp + (size_t)(2 * cp)     * HW + r);
        float2 y1 = *(const float2*)(Bp + (size_t)(2 * cp + 1) * HW + r);
        sts32(sb + BH_OFF + o0, pack2h(y0.x * 0.125f, y1.x * 0.125f));
        sts32(sb + BH_OFF + o1, pack2h(y0.y * 0.125f, y1.y * 0.125f));
    }
    __syncthreads();

    // ---- MMA mainloop: 4 k-steps x 2 terms (Ah*B + Al*B) ----
    float acc[2][8][4];
#pragma unroll
    for (int i = 0; i < 2; i++)
#pragma unroll
        for (int j = 0; j < 8; j++)
#pragma unroll
            for (int q = 0; q < 4; q++) acc[i][j][q] = 0.0f;

    const int a_row = wm * 32 + (lane & 7) + ((lane >> 3) & 1) * 8;
    const int a_kb  = (lane >> 4) * 16;
    const int b_row = wn * 64 + (lane & 7) + (lane >> 4) * 8;
    const int b_kb  = ((lane >> 3) & 1) * 16;

#pragma unroll
    for (int ks = 0; ks < 4; ks++) {
        const int kbase = ks * 32;
        uint32_t ah[2][4], al[2][4], bf[16];
#pragma unroll
        for (int mi = 0; mi < 2; mi++)
            ldsm4(sb + AH_OFF + swz((uint32_t)((a_row + mi * 16) * 128 + kbase + a_kb)), ah[mi]);
#pragma unroll
        for (int jp = 0; jp < 4; jp++)
            ldsm4(sb + BH_OFF + swz((uint32_t)((b_row + jp * 16) * 128 + kbase + b_kb)), &bf[jp * 4]);
#pragma unroll
        for (int mi = 0; mi < 2; mi++)
            ldsm4(sb + AL_OFF + swz((uint32_t)((a_row + mi * 16) * 128 + kbase + a_kb)), al[mi]);
#pragma unroll
        for (int mi = 0; mi < 2; mi++)
#pragma unroll
            for (int ni = 0; ni < 8; ni++)
                mma16816(acc[mi][ni], ah[mi], &bf[ni * 2]);
#pragma unroll
        for (int mi = 0; mi < 2; mi++)
#pragma unroll
            for (int ni = 0; ni < 8; ni++)
                mma16816(acc[mi][ni], al[mi], &bf[ni * 2]);
    }

    // ---- exp in place + per-thread column partial sums ----
    float cs[16];
#pragma unroll
    for (int q = 0; q < 16; q++) cs[q] = 0.0f;
#pragma unroll
    for (int mi = 0; mi < 2; mi++)
#pragma unroll
        for (int ni = 0; ni < 8; ni++) {
            acc[mi][ni][0] = __expf(acc[mi][ni][0]);
            acc[mi][ni][1] = __expf(acc[mi][ni][1]);
            acc[mi][ni][2] = __expf(acc[mi][ni][2]);
            acc[mi][ni][3] = __expf(acc[mi][ni][3]);
            cs[2 * ni]     += acc[mi][ni][0] + acc[mi][ni][2];
            cs[2 * ni + 1] += acc[mi][ni][1] + acc[mi][ni][3];
        }
#pragma unroll
    for (int msk = 4; msk < 32; msk <<= 1)
#pragma unroll
        for (int q = 0; q < 16; q++)
            cs[q] += __shfl_xor_sync(0xFFFFFFFFu, cs[q], msk);

    if (lane < 4) {
        float* red = (float*)(smem + RED_OFF);
#pragma unroll
        for (int ni = 0; ni < 8; ni++) {
            atomicAdd(&red[wn * 64 + ni * 8 + 2 * lane],     cs[2 * ni]);
            atomicAdd(&red[wn * 64 + ni * 8 + 2 * lane + 1], cs[2 * ni + 1]);
        }
    }
    __syncthreads();

    // ---- contribute to global column sums, then signal ----
    float* gs = &g_sums[b * HW + n0];
    if (tid < 128) {
        atomicAdd(&gs[tid], ((float*)(smem + RED_OFF))[tid]);
        __threadfence();
    }
    __syncthreads();
    if (tid == 0) {
        atomicAdd(&g_cnt[grp], 1u);
        while (atomicAdd(&g_cnt[grp], 0u) < GROUP_CTAS) __nanosleep(128);
    }
    __syncthreads();

    // ---- read final sums (L2-coherent), normalize in registers, store once ----
    const int mrow = m0 + wm * 32 + (lane >> 2);
    const int ncol_l = wn * 64 + 2 * (lane & 3);     // local column base
    float rs[16];
#pragma unroll
    for (int ni = 0; ni < 8; ni++) {
        rs[2 * ni]     = __fdividef(1.0f, __ldcg(&gs[ncol_l + ni * 8]));
        rs[2 * ni + 1] = __fdividef(1.0f, __ldcg(&gs[ncol_l + ni * 8 + 1]));
    }
#pragma unroll
    for (int mi = 0; mi < 2; mi++) {
#pragma unroll
        for (int ni = 0; ni < 8; ni++) {
            size_t ro = (size_t)(b * HW + mrow + mi * 16) * HW + n0 + ncol_l + ni * 8;
            *(float2*)(out + ro) =
                make_float2(acc[mi][ni][0] * rs[2 * ni], acc[mi][ni][1] * rs[2 * ni + 1]);
            *(float2*)(out + ro + (size_t)8 * HW) =
                make_float2(acc[mi][ni][2] * rs[2 * ni], acc[mi][ni][3] * rs[2 * ni + 1]);
        }
    }
}

extern "C" void kernel_launch(void* const* d_in, const int* in_sizes, int n_in,
                              void* d_out, int out_size) {
    const float* Mk = (const float*)d_in[0];
    const float* Qk = (const float*)d_in[1];
    float* out = (float*)d_out;

    cudaFuncSetAttribute(gemm_softmax_fused,
                         cudaFuncAttributeMaxDynamicSharedMemorySize, SMEM_BYTES);

    init_kernel<<<(BATCH * HW + 255) / 256, 256>>>();

    gemm_softmax_fused<<<BATCH * 32 * 32, 256, SMEM_BYTES>>>(Mk, Qk, out);
}

// round 6
// speedup vs baseline: 2.1425x; 1.0559x over previous
#include <cuda_runtime.h>
#include <cuda_fp16.h>
#include <stdint.h>

// Problem constants: B=8, CK=64, H=W=64 -> HW=4096
#define BATCH 8
#define CKDIM 64
#define HW    4096
#define NGROUPS 256           // (b, n_tile) column groups: 8 * 32
#define GROUP_CTAS 32         // m-tiles per group

// Dynamic SMEM: A hi/lo (fp16) + B (fp16) K-major SW128 tiles + reduce + ticket
#define AH_OFF 0        // Mk hi   128 x 64 fp16 = 16 KB
#define AL_OFF 16384    // Mk lo
#define BH_OFF 32768    // Qk/8    128 x 64 fp16 = 16 KB
#define RED_OFF 49152   // 128 floats column-sum reduce
#define TKT_OFF (49152 + 512)
#define SMEM_BYTES (49152 + 512 + 16)

__device__ float g_sums[BATCH * HW];
__device__ unsigned g_cnt[NGROUPS];
__device__ unsigned g_ticket;

__global__ void init_kernel() {
    int i = blockIdx.x * blockDim.x + threadIdx.x;
    if (i < BATCH * HW) g_sums[i] = 0.0f;
    if (i < NGROUPS) g_cnt[i] = 0u;
    if (i == 0) g_ticket = 0u;
}

__device__ __forceinline__ uint32_t smem_u32(const void* p) {
    uint32_t a;
    asm("{ .reg .u64 t; cvta.to.shared.u64 t, %1; cvt.u32.u64 %0, t; }"
        : "=r"(a) : "l"(p));
    return a;
}
__device__ __forceinline__ uint32_t swz(uint32_t off) {
    return off ^ ((off >> 3) & 0x70);
}
__device__ __forceinline__ void split2h(float v0, float v1, uint32_t& hi, uint32_t& lo) {
    __half2 h = __floats2half2_rn(v0, v1);
    float2 hf = __half22float2(h);
    __half2 l = __floats2half2_rn(v0 - hf.x, v1 - hf.y);
    hi = *(uint32_t*)&h;
    lo = *(uint32_t*)&l;
}
__device__ __forceinline__ uint32_t pack2h(float v0, float v1) {
    __half2 h = __floats2half2_rn(v0, v1);
    return *(uint32_t*)&h;
}
__device__ __forceinline__ void sts32(uint32_t addr, uint32_t v) {
    asm volatile("st.shared.b32 [%0], %1;" :: "r"(addr), "r"(v));
}
__device__ __forceinline__ void ldsm4(uint32_t addr, uint32_t* r) {
    asm volatile("ldmatrix.sync.aligned.m8n8.x4.shared.b16 {%0,%1,%2,%3}, [%4];"
                 : "=r"(r[0]), "=r"(r[1]), "=r"(r[2]), "=r"(r[3]) : "r"(addr));
}
__device__ __forceinline__ void mma16816(float* d, const uint32_t* a, const uint32_t* b) {
    asm volatile(
        "mma.sync.aligned.m16n8k16.row.col.f32.f16.f16.f32 "
        "{%0,%1,%2,%3}, {%4,%5,%6,%7}, {%8,%9}, {%0,%1,%2,%3};"
        : "+f"(d[0]), "+f"(d[1]), "+f"(d[2]), "+f"(d[3])
        : "r"(a[0]), "r"(a[1]), "r"(a[2]), "r"(a[3]), "r"(b[0]), "r"(b[1]));
}

// Fused GEMM + exp + cross-CTA column-sum exchange + in-register normalize.
// 512 threads, 4x4 warp grid, 32x32 warp tiles -> 32 acc regs/thread,
// 2 CTAs/SM = 32 warps (50% occ) for latency hiding.
__global__ __launch_bounds__(512, 2)
void gemm_softmax_fused(const float* __restrict__ Mk, const float* __restrict__ Qk,
                        float* __restrict__ out) {
    extern __shared__ char smem[];
    const uint32_t sb = smem_u32(smem);
    const int tid = threadIdx.x, lane = tid & 31, wid = tid >> 5;
    const int wm = wid >> 2, wn = wid & 3;           // 4x4 warp grid

    // --- ticket-based tile assignment: group = 32 consecutive tickets ---
    if (tid == 0)
        *(unsigned*)(smem + TKT_OFF) = atomicAdd(&g_ticket, 1u);
    if (tid < 128) ((float*)(smem + RED_OFF))[tid] = 0.0f;
    __syncthreads();
    const unsigned tkt = *(const unsigned*)(smem + TKT_OFF);
    const int m_tile = (int)(tkt & 31u);
    const unsigned grp = tkt >> 5;                   // 0..255
    const int n_tile = (int)(grp & 31u);
    const int b      = (int)(grp >> 5);
    const int m0 = m_tile * 128, n0 = n_tile * 128;

    const float* Ap = Mk + (size_t)b * CKDIM * HW + m0;
    const float* Bp = Qk + (size_t)b * CKDIM * HW + n0;

    // ---- load + convert, K-major SW128 rows (same bijection, 4 iters/thread) ----
#pragma unroll
    for (int it = 0; it < 4; it++) {
        int u  = tid + it * 512;                     // 0..2047
        int r  = ((u & 15) + (u >> 9) * 16) * 2;     // even row 0..126
        int cp = ((u >> 4) & 1) + ((u >> 5) & 15) * 2;
        uint32_t o0 = swz((uint32_t)(r * 128 + cp * 4));
        uint32_t o1 = swz((uint32_t)((r + 1) * 128 + cp * 4));
        float2 x0 = *(const float2*)(Ap + (size_t)(2 * cp)     * HW + r);
        float2 x1 = *(const float2*)(Ap + (size_t)(2 * cp + 1) * HW + r);
        uint32_t hi, lo;
        split2h(x0.x, x1.x, hi, lo);
        sts32(sb + AH_OFF + o0, hi); sts32(sb + AL_OFF + o0, lo);
        split2h(x0.y, x1.y, hi, lo);
        sts32(sb + AH_OFF + o1, hi); sts32(sb + AL_OFF + o1, lo);
        float2 y0 = *(const float2*)(Bp + (size_t)(2 * cp)     * HW + r);
        float2 y1 = *(const float2*)(Bp + (size_t)(2 * cp + 1) * HW + r);
        sts32(sb + BH_OFF + o0, pack2h(y0.x * 0.125f, y1.x * 0.125f));
        sts32(sb + BH_OFF + o1, pack2h(y0.y * 0.125f, y1.y * 0.125f));
    }
    __syncthreads();

    // ---- MMA mainloop: 4 k-steps x 2 terms (Ah*B + Al*B) ----
    float acc[2][4][4];
#pragma unroll
    for (int i = 0; i < 2; i++)
#pragma unroll
        for (int j = 0; j < 4; j++)
#pragma unroll
            for (int q = 0; q < 4; q++) acc[i][j][q] = 0.0f;

    const int a_row = wm * 32 + (lane & 7) + ((lane >> 3) & 1) * 8;
    const int a_kb  = (lane >> 4) * 16;
    const int b_row = wn * 32 + (lane & 7) + (lane >> 4) * 8;
    const int b_kb  = ((lane >> 3) & 1) * 16;

#pragma unroll
    for (int ks = 0; ks < 4; ks++) {
        const int kbase = ks * 32;
        uint32_t ah[2][4], al[2][4], bf[8];
#pragma unroll
        for (int mi = 0; mi < 2; mi++)
            ldsm4(sb + AH_OFF + swz((uint32_t)((a_row + mi * 16) * 128 + kbase + a_kb)), ah[mi]);
#pragma unroll
        for (int jp = 0; jp < 2; jp++)
            ldsm4(sb + BH_OFF + swz((uint32_t)((b_row + jp * 16) * 128 + kbase + b_kb)), &bf[jp * 4]);
#pragma unroll
        for (int mi = 0; mi < 2; mi++)
            ldsm4(sb + AL_OFF + swz((uint32_t)((a_row + mi * 16) * 128 + kbase + a_kb)), al[mi]);
#pragma unroll
        for (int mi = 0; mi < 2; mi++)
#pragma unroll
            for (int ni = 0; ni < 4; ni++)
                mma16816(acc[mi][ni], ah[mi], &bf[ni * 2]);
#pragma unroll
        for (int mi = 0; mi < 2; mi++)
#pragma unroll
            for (int ni = 0; ni < 4; ni++)
                mma16816(acc[mi][ni], al[mi], &bf[ni * 2]);
    }

    // ---- exp in place + per-thread column partial sums ----
    float cs[8];
#pragma unroll
    for (int q = 0; q < 8; q++) cs[q] = 0.0f;
#pragma unroll
    for (int mi = 0; mi < 2; mi++)
#pragma unroll
        for (int ni = 0; ni < 4; ni++) {
            acc[mi][ni][0] = __expf(acc[mi][ni][0]);
            acc[mi][ni][1] = __expf(acc[mi][ni][1]);
            acc[mi][ni][2] = __expf(acc[mi][ni][2]);
            acc[mi][ni][3] = __expf(acc[mi][ni][3]);
            cs[2 * ni]     += acc[mi][ni][0] + acc[mi][ni][2];
            cs[2 * ni + 1] += acc[mi][ni][1] + acc[mi][ni][3];
        }
#pragma unroll
    for (int msk = 4; msk < 32; msk <<= 1)
#pragma unroll
        for (int q = 0; q < 8; q++)
            cs[q] += __shfl_xor_sync(0xFFFFFFFFu, cs[q], msk);

    if (lane < 4) {
        float* red = (float*)(smem + RED_OFF);
#pragma unroll
        for (int ni = 0; ni < 4; ni++) {
            atomicAdd(&red[wn * 32 + ni * 8 + 2 * lane],     cs[2 * ni]);
            atomicAdd(&red[wn * 32 + ni * 8 + 2 * lane + 1], cs[2 * ni + 1]);
        }
    }
    __syncthreads();

    // ---- contribute to global column sums, then signal / spin ----
    float* gs = &g_sums[b * HW + n0];
    if (tid < 128) {
        atomicAdd(&gs[tid], ((float*)(smem + RED_OFF))[tid]);
        __threadfence();
    }
    __syncthreads();
    if (tid == 0) {
        atomicAdd(&g_cnt[grp], 1u);
        while (atomicAdd(&g_cnt[grp], 0u) < GROUP_CTAS) __nanosleep(128);
    }
    __syncthreads();

    // ---- read final sums (L2-coherent), normalize in registers, store once ----
    const int mrow = m0 + wm * 32 + (lane >> 2);
    const int ncol_l = wn * 32 + 2 * (lane & 3);
    float rs[8];
#pragma unroll
    for (int ni = 0; ni < 4; ni++) {
        rs[2 * ni]     = __fdividef(1.0f, __ldcg(&gs[ncol_l + ni * 8]));
        rs[2 * ni + 1] = __fdividef(1.0f, __ldcg(&gs[ncol_l + ni * 8 + 1]));
    }
#pragma unroll
    for (int mi = 0; mi < 2; mi++) {
#pragma unroll
        for (int ni = 0; ni < 4; ni++) {
            size_t ro = (size_t)(b * HW + mrow + mi * 16) * HW + n0 + ncol_l + ni * 8;
            *(float2*)(out + ro) =
                make_float2(acc[mi][ni][0] * rs[2 * ni], acc[mi][ni][1] * rs[2 * ni + 1]);
            *(float2*)(out + ro + (size_t)8 * HW) =
                make_float2(acc[mi][ni][2] * rs[2 * ni], acc[mi][ni][3] * rs[2 * ni + 1]);
        }
    }
}

extern "C" void kernel_launch(void* const* d_in, const int* in_sizes, int n_in,
                              void* d_out, int out_size) {
    const float* Mk = (const float*)d_in[0];
    const float* Qk = (const float*)d_in[1];
    float* out = (float*)d_out;

    cudaFuncSetAttribute(gemm_softmax_fused,
                         cudaFuncAttributeMaxDynamicSharedMemorySize, SMEM_BYTES);

    init_kernel<<<(BATCH * HW + 255) / 256, 256>>>();

    gemm_softmax_fused<<<BATCH * 32 * 32, 512, SMEM_BYTES>>>(Mk, Qk, out);
}

// round 7
// speedup vs baseline: 2.2389x; 1.0450x over previous
#include <cuda_runtime.h>
#include <cuda_fp16.h>
#include <stdint.h>

// Problem constants: B=8, CK=64, H=W=64 -> HW=4096
#define BATCH 8
#define CKDIM 64
#define HW    4096
#define NGROUPS 256           // (b, n_tile) column groups: 8 * 32
#define GROUP_CTAS 32         // m-tiles per group

// Dynamic SMEM: A hi/lo (fp16) + B (fp16) K-major SW128 tiles + reduce + ticket
#define AH_OFF 0        // Mk hi   128 x 64 fp16 = 16 KB
#define AL_OFF 16384    // Mk lo
#define BH_OFF 32768    // Qk/8    128 x 64 fp16 = 16 KB
#define RED_OFF 49152   // 128 floats column-sum reduce
#define TKT_OFF (49152 + 512)
#define SMEM_BYTES (49152 + 512 + 16)

__device__ float g_sums[BATCH * HW];
__device__ unsigned g_cnt[NGROUPS];
__device__ unsigned g_ticket;

__global__ void init_kernel() {
    int i = blockIdx.x * blockDim.x + threadIdx.x;
    if (i < BATCH * HW) g_sums[i] = 0.0f;
    if (i < NGROUPS) g_cnt[i] = 0u;
    if (i == 0) g_ticket = 0u;
}

__device__ __forceinline__ uint32_t smem_u32(const void* p) {
    uint32_t a;
    asm("{ .reg .u64 t; cvta.to.shared.u64 t, %1; cvt.u32.u64 %0, t; }"
        : "=r"(a) : "l"(p));
    return a;
}
__device__ __forceinline__ uint32_t swz(uint32_t off) {
    return off ^ ((off >> 3) & 0x70);
}
__device__ __forceinline__ void split2h(float v0, float v1, uint32_t& hi, uint32_t& lo) {
    __half2 h = __floats2half2_rn(v0, v1);
    float2 hf = __half22float2(h);
    __half2 l = __floats2half2_rn(v0 - hf.x, v1 - hf.y);
    hi = *(uint32_t*)&h;
    lo = *(uint32_t*)&l;
}
__device__ __forceinline__ uint32_t pack2h(float v0, float v1) {
    __half2 h = __floats2half2_rn(v0, v1);
    return *(uint32_t*)&h;
}
__device__ __forceinline__ void sts128(uint32_t addr, uint32_t r0, uint32_t r1,
                                       uint32_t r2, uint32_t r3) {
    asm volatile("st.shared.v4.b32 [%0], {%1,%2,%3,%4};"
                 :: "r"(addr), "r"(r0), "r"(r1), "r"(r2), "r"(r3));
}
__device__ __forceinline__ void ldsm4(uint32_t addr, uint32_t* r) {
    asm volatile("ldmatrix.sync.aligned.m8n8.x4.shared.b16 {%0,%1,%2,%3}, [%4];"
                 : "=r"(r[0]), "=r"(r[1]), "=r"(r[2]), "=r"(r[3]) : "r"(addr));
}
__device__ __forceinline__ void mma16816(float* d, const uint32_t* a, const uint32_t* b) {
    asm volatile(
        "mma.sync.aligned.m16n8k16.row.col.f32.f16.f16.f32 "
        "{%0,%1,%2,%3}, {%4,%5,%6,%7}, {%8,%9}, {%0,%1,%2,%3};"
        : "+f"(d[0]), "+f"(d[1]), "+f"(d[2]), "+f"(d[3])
        : "r"(a[0]), "r"(a[1]), "r"(a[2]), "r"(a[3]), "r"(b[0]), "r"(b[1]));
}

// Fused GEMM + exp + cross-CTA column-sum exchange + in-register normalize.
// 512 threads, 4x4 warp grid, 32x32 warp tiles. Load phase writes SMEM with
// conflict-free STS.128 (one 16B swizzle block per store).
__global__ __launch_bounds__(512, 2)
void gemm_softmax_fused(const float* __restrict__ Mk, const float* __restrict__ Qk,
                        float* __restrict__ out) {
    extern __shared__ char smem[];
    const uint32_t sb = smem_u32(smem);
    const int tid = threadIdx.x, lane = tid & 31, wid = tid >> 5;
    const int wm = wid >> 2, wn = wid & 3;           // 4x4 warp grid

    // --- ticket-based tile assignment: group = 32 consecutive tickets ---
    if (tid == 0)
        *(unsigned*)(smem + TKT_OFF) = atomicAdd(&g_ticket, 1u);
    if (tid < 128) ((float*)(smem + RED_OFF))[tid] = 0.0f;
    __syncthreads();
    const unsigned tkt = *(const unsigned*)(smem + TKT_OFF);
    const int m_tile = (int)(tkt & 31u);
    const unsigned grp = tkt >> 5;                   // 0..255
    const int n_tile = (int)(grp & 31u);
    const int b      = (int)(grp >> 5);
    const int m0 = m_tile * 128, n0 = n_tile * 128;

    const float* Ap = Mk + (size_t)b * CKDIM * HW + m0;
    const float* Bp = Qk + (size_t)b * CKDIM * HW + n0;

    // ---- load + convert: thread handles (row r, 16B k-block kb) per iter ----
    // slot = wid*2 + it  in [0,32): rg = slot>>3 (4 groups of 32 rows), kb = slot&7.
    // 8 LDG.32 per array (c = kb*8+j, coalesced 128B across lanes), then one
    // STS.128 per array at swizzled block (r, kb): unit = kb ^ (r&7) -> no conflicts.
#pragma unroll
    for (int it = 0; it < 2; it++) {
        const int slot = wid * 2 + it;
        const int rg = slot >> 3, kb = slot & 7;
        const int r = rg * 32 + lane;
        const int c0 = kb * 8;
        float a[8], bv[8];
#pragma unroll
        for (int j = 0; j < 8; j++) a[j]  = Ap[(size_t)(c0 + j) * HW + r];
#pragma unroll
        for (int j = 0; j < 8; j++) bv[j] = Bp[(size_t)(c0 + j) * HW + r] * 0.125f;
        uint32_t hi[4], lo[4], bw[4];
#pragma unroll
        for (int j = 0; j < 4; j++) {
            split2h(a[2 * j], a[2 * j + 1], hi[j], lo[j]);
            bw[j] = pack2h(bv[2 * j], bv[2 * j + 1]);
        }
        const uint32_t sa = swz((uint32_t)(r * 128 + kb * 16));
        sts128(sb + AH_OFF + sa, hi[0], hi[1], hi[2], hi[3]);
        sts128(sb + AL_OFF + sa, lo[0], lo[1], lo[2], lo[3]);
        sts128(sb + BH_OFF + sa, bw[0], bw[1], bw[2], bw[3]);
    }
    __syncthreads();

    // ---- MMA mainloop: 4 k-steps x 2 terms (Ah*B + Al*B) ----
    float acc[2][4][4];
#pragma unroll
    for (int i = 0; i < 2; i++)
#pragma unroll
        for (int j = 0; j < 4; j++)
#pragma unroll
            for (int q = 0; q < 4; q++) acc[i][j][q] = 0.0f;

    const int a_row = wm * 32 + (lane & 7) + ((lane >> 3) & 1) * 8;
    const int a_kb  = (lane >> 4) * 16;
    const int b_row = wn * 32 + (lane & 7) + (lane >> 4) * 8;
    const int b_kb  = ((lane >> 3) & 1) * 16;

#pragma unroll
    for (int ks = 0; ks < 4; ks++) {
        const int kbase = ks * 32;
        uint32_t ah[2][4], al[2][4], bf[8];
#pragma unroll
        for (int mi = 0; mi < 2; mi++)
            ldsm4(sb + AH_OFF + swz((uint32_t)((a_row + mi * 16) * 128 + kbase + a_kb)), ah[mi]);
#pragma unroll
        for (int jp = 0; jp < 2; jp++)
            ldsm4(sb + BH_OFF + swz((uint32_t)((b_row + jp * 16) * 128 + kbase + b_kb)), &bf[jp * 4]);
#pragma unroll
        for (int mi = 0; mi < 2; mi++)
            ldsm4(sb + AL_OFF + swz((uint32_t)((a_row + mi * 16) * 128 + kbase + a_kb)), al[mi]);
#pragma unroll
        for (int mi = 0; mi < 2; mi++)
#pragma unroll
            for (int ni = 0; ni < 4; ni++)
                mma16816(acc[mi][ni], ah[mi], &bf[ni * 2]);
#pragma unroll
        for (int mi = 0; mi < 2; mi++)
#pragma unroll
            for (int ni = 0; ni < 4; ni++)
                mma16816(acc[mi][ni], al[mi], &bf[ni * 2]);
    }

    // ---- exp in place + per-thread column partial sums ----
    float cs[8];
#pragma unroll
    for (int q = 0; q < 8; q++) cs[q] = 0.0f;
#pragma unroll
    for (int mi = 0; mi < 2; mi++)
#pragma unroll
        for (int ni = 0; ni < 4; ni++) {
            acc[mi][ni][0] = __expf(acc[mi][ni][0]);
            acc[mi][ni][1] = __expf(acc[mi][ni][1]);
            acc[mi][ni][2] = __expf(acc[mi][ni][2]);
            acc[mi][ni][3] = __expf(acc[mi][ni][3]);
            cs[2 * ni]     += acc[mi][ni][0] + acc[mi][ni][2];
            cs[2 * ni + 1] += acc[mi][ni][1] + acc[mi][ni][3];
        }
#pragma unroll
    for (int msk = 4; msk < 32; msk <<= 1)
#pragma unroll
        for (int q = 0; q < 8; q++)
            cs[q] += __shfl_xor_sync(0xFFFFFFFFu, cs[q], msk);

    if (lane < 4) {
        float* red = (float*)(smem + RED_OFF);
#pragma unroll
        for (int ni = 0; ni < 4; ni++) {
            atomicAdd(&red[wn * 32 + ni * 8 + 2 * lane],     cs[2 * ni]);
            atomicAdd(&red[wn * 32 + ni * 8 + 2 * lane + 1], cs[2 * ni + 1]);
        }
    }
    __syncthreads();

    // ---- contribute to global column sums, then signal / spin ----
    float* gs = &g_sums[b * HW + n0];
    if (tid < 128) {
        atomicAdd(&gs[tid], ((float*)(smem + RED_OFF))[tid]);
        __threadfence();
    }
    __syncthreads();
    if (tid == 0) {
        atomicAdd(&g_cnt[grp], 1u);
        while (atomicAdd(&g_cnt[grp], 0u) < GROUP_CTAS) __nanosleep(128);
    }
    __syncthreads();

    // ---- read final sums (L2-coherent), normalize in registers, store once ----
    const int mrow = m0 + wm * 32 + (lane >> 2);
    const int ncol_l = wn * 32 + 2 * (lane & 3);
    float rs[8];
#pragma unroll
    for (int ni = 0; ni < 4; ni++) {
        rs[2 * ni]     = __fdividef(1.0f, __ldcg(&gs[ncol_l + ni * 8]));
        rs[2 * ni + 1] = __fdividef(1.0f, __ldcg(&gs[ncol_l + ni * 8 + 1]));
    }
#pragma unroll
    for (int mi = 0; mi < 2; mi++) {
#pragma unroll
        for (int ni = 0; ni < 4; ni++) {
            size_t ro = (size_t)(b * HW + mrow + mi * 16) * HW + n0 + ncol_l + ni * 8;
            __stcs((float2*)(out + ro),
                   make_float2(acc[mi][ni][0] * rs[2 * ni], acc[mi][ni][1] * rs[2 * ni + 1]));
            __stcs((float2*)(out + ro + (size_t)8 * HW),
                   make_float2(acc[mi][ni][2] * rs[2 * ni], acc[mi][ni][3] * rs[2 * ni + 1]));
        }
    }
}

extern "C" void kernel_launch(void* const* d_in, const int* in_sizes, int n_in,
                              void* d_out, int out_size) {
    const float* Mk = (const float*)d_in[0];
    const float* Qk = (const float*)d_in[1];
    float* out = (float*)d_out;

    cudaFuncSetAttribute(gemm_softmax_fused,
                         cudaFuncAttributeMaxDynamicSharedMemorySize, SMEM_BYTES);

    init_kernel<<<(BATCH * HW + 255) / 256, 256>>>();

    gemm_softmax_fused<<<BATCH * 32 * 32, 512, SMEM_BYTES>>>(Mk, Qk, out);
}

// round 8
// speedup vs baseline: 2.3057x; 1.0298x over previous
#include <cuda_runtime.h>
#include <cuda_fp16.h>
#include <stdint.h>

// Problem constants: B=8, CK=64, H=W=64 -> HW=4096
#define BATCH 8
#define CKDIM 64
#define HW    4096
#define NGROUPS 256           // (b, n_tile) column groups: 8 * 32
#define GROUP_CTAS 32         // m-tiles per group

// Dynamic SMEM: A (fp16) + B (fp16) K-major SW128 tiles + reduce + ticket
#define AH_OFF 0        // Mk      128 x 64 fp16 = 16 KB
#define BH_OFF 16384    // Qk/8    128 x 64 fp16 = 16 KB
#define RED_OFF 32768   // 128 floats column-sum reduce
#define TKT_OFF (32768 + 512)
#define SMEM_BYTES (32768 + 512 + 16)

__device__ float g_sums[BATCH * HW];
__device__ unsigned g_cnt[NGROUPS];
__device__ unsigned g_ticket;

__global__ void init_kernel() {
    int i = blockIdx.x * blockDim.x + threadIdx.x;
    if (i < BATCH * HW) g_sums[i] = 0.0f;
    if (i < NGROUPS) g_cnt[i] = 0u;
    if (i == 0) g_ticket = 0u;
}

__device__ __forceinline__ uint32_t smem_u32(const void* p) {
    uint32_t a;
    asm("{ .reg .u64 t; cvta.to.shared.u64 t, %1; cvt.u32.u64 %0, t; }"
        : "=r"(a) : "l"(p));
    return a;
}
__device__ __forceinline__ uint32_t swz(uint32_t off) {
    return off ^ ((off >> 3) & 0x70);
}
__device__ __forceinline__ uint32_t pack2h(float v0, float v1) {
    __half2 h = __floats2half2_rn(v0, v1);
    return *(uint32_t*)&h;
}
__device__ __forceinline__ void sts128(uint32_t addr, uint32_t r0, uint32_t r1,
                                       uint32_t r2, uint32_t r3) {
    asm volatile("st.shared.v4.b32 [%0], {%1,%2,%3,%4};"
                 :: "r"(addr), "r"(r0), "r"(r1), "r"(r2), "r"(r3));
}
__device__ __forceinline__ void ldsm4(uint32_t addr, uint32_t* r) {
    asm volatile("ldmatrix.sync.aligned.m8n8.x4.shared.b16 {%0,%1,%2,%3}, [%4];"
                 : "=r"(r[0]), "=r"(r[1]), "=r"(r[2]), "=r"(r[3]) : "r"(addr));
}
__device__ __forceinline__ void mma16816(float* d, const uint32_t* a, const uint32_t* b) {
    asm volatile(
        "mma.sync.aligned.m16n8k16.row.col.f32.f16.f16.f32 "
        "{%0,%1,%2,%3}, {%4,%5,%6,%7}, {%8,%9}, {%0,%1,%2,%3};"
        : "+f"(d[0]), "+f"(d[1]), "+f"(d[2]), "+f"(d[3])
        : "r"(a[0]), "r"(a[1]), "r"(a[2]), "r"(a[3]), "r"(b[0]), "r"(b[1]));
}

// Fused GEMM + exp + cross-CTA column-sum exchange + in-register normalize.
// Single fp16 term (A and B both rounded once): rel_err ~3e-4 < 1e-3.
__global__ __launch_bounds__(512, 2)
void gemm_softmax_fused(const float* __restrict__ Mk, const float* __restrict__ Qk,
                        float* __restrict__ out) {
    extern __shared__ char smem[];
    const uint32_t sb = smem_u32(smem);
    const int tid = threadIdx.x, lane = tid & 31, wid = tid >> 5;
    const int wm = wid >> 2, wn = wid & 3;           // 4x4 warp grid

    // --- ticket-based tile assignment: group = 32 consecutive tickets ---
    if (tid == 0)
        *(unsigned*)(smem + TKT_OFF) = atomicAdd(&g_ticket, 1u);
    if (tid < 128) ((float*)(smem + RED_OFF))[tid] = 0.0f;
    __syncthreads();
    const unsigned tkt = *(const unsigned*)(smem + TKT_OFF);
    const int m_tile = (int)(tkt & 31u);
    const unsigned grp = tkt >> 5;                   // 0..255
    const int n_tile = (int)(grp & 31u);
    const int b      = (int)(grp >> 5);
    const int m0 = m_tile * 128, n0 = n_tile * 128;

    const float* Ap = Mk + (size_t)b * CKDIM * HW + m0;
    const float* Bp = Qk + (size_t)b * CKDIM * HW + n0;

    // ---- load + convert: thread handles (row r, 16B k-block kb) per iter ----
    // Conflict-free STS.128: unit = kb ^ (r&7) distinct across lanes 0..7.
#pragma unroll
    for (int it = 0; it < 2; it++) {
        const int slot = wid * 2 + it;
        const int rg = slot >> 3, kb = slot & 7;
        const int r = rg * 32 + lane;
        const int c0 = kb * 8;
        float a[8], bv[8];
#pragma unroll
        for (int j = 0; j < 8; j++) a[j]  = Ap[(size_t)(c0 + j) * HW + r];
#pragma unroll
        for (int j = 0; j < 8; j++) bv[j] = Bp[(size_t)(c0 + j) * HW + r] * 0.125f;
        uint32_t aw[4], bw[4];
#pragma unroll
        for (int j = 0; j < 4; j++) {
            aw[j] = pack2h(a[2 * j],  a[2 * j + 1]);
            bw[j] = pack2h(bv[2 * j], bv[2 * j + 1]);
        }
        const uint32_t sa = swz((uint32_t)(r * 128 + kb * 16));
        sts128(sb + AH_OFF + sa, aw[0], aw[1], aw[2], aw[3]);
        sts128(sb + BH_OFF + sa, bw[0], bw[1], bw[2], bw[3]);
    }
    __syncthreads();

    // ---- MMA mainloop: 4 k-steps, single term ----
    float acc[2][4][4];
#pragma unroll
    for (int i = 0; i < 2; i++)
#pragma unroll
        for (int j = 0; j < 4; j++)
#pragma unroll
            for (int q = 0; q < 4; q++) acc[i][j][q] = 0.0f;

    const int a_row = wm * 32 + (lane & 7) + ((lane >> 3) & 1) * 8;
    const int a_kb  = (lane >> 4) * 16;
    const int b_row = wn * 32 + (lane & 7) + (lane >> 4) * 8;
    const int b_kb  = ((lane >> 3) & 1) * 16;

#pragma unroll
    for (int ks = 0; ks < 4; ks++) {
        const int kbase = ks * 32;
        uint32_t ah[2][4], bf[8];
#pragma unroll
        for (int mi = 0; mi < 2; mi++)
            ldsm4(sb + AH_OFF + swz((uint32_t)((a_row + mi * 16) * 128 + kbase + a_kb)), ah[mi]);
#pragma unroll
        for (int jp = 0; jp < 2; jp++)
            ldsm4(sb + BH_OFF + swz((uint32_t)((b_row + jp * 16) * 128 + kbase + b_kb)), &bf[jp * 4]);
#pragma unroll
        for (int mi = 0; mi < 2; mi++)
#pragma unroll
            for (int ni = 0; ni < 4; ni++)
                mma16816(acc[mi][ni], ah[mi], &bf[ni * 2]);
    }

    // ---- exp in place + per-thread column partial sums ----
    float cs[8];
#pragma unroll
    for (int q = 0; q < 8; q++) cs[q] = 0.0f;
#pragma unroll
    for (int mi = 0; mi < 2; mi++)
#pragma unroll
        for (int ni = 0; ni < 4; ni++) {
            acc[mi][ni][0] = __expf(acc[mi][ni][0]);
            acc[mi][ni][1] = __expf(acc[mi][ni][1]);
            acc[mi][ni][2] = __expf(acc[mi][ni][2]);
            acc[mi][ni][3] = __expf(acc[mi][ni][3]);
            cs[2 * ni]     += acc[mi][ni][0] + acc[mi][ni][2];
            cs[2 * ni + 1] += acc[mi][ni][1] + acc[mi][ni][3];
        }
#pragma unroll
    for (int msk = 4; msk < 32; msk <<= 1)
#pragma unroll
        for (int q = 0; q < 8; q++)
            cs[q] += __shfl_xor_sync(0xFFFFFFFFu, cs[q], msk);

    if (lane < 4) {
        float* red = (float*)(smem + RED_OFF);
#pragma unroll
        for (int ni = 0; ni < 4; ni++) {
            atomicAdd(&red[wn * 32 + ni * 8 + 2 * lane],     cs[2 * ni]);
            atomicAdd(&red[wn * 32 + ni * 8 + 2 * lane + 1], cs[2 * ni + 1]);
        }
    }
    __syncthreads();

    // ---- contribute to global column sums ----
    float* gs = &g_sums[b * HW + n0];
    if (tid < 128)
        atomicAdd(&gs[tid], ((float*)(smem + RED_OFF))[tid]);
    __syncthreads();

    // ---- signal (release) / wait (acquire): syncthreads edge publishes all
    //      contributors' atomics through tid0's release. ----
    if (tid == 0) {
        unsigned* cnt = &g_cnt[grp];
        asm volatile("red.release.gpu.global.add.u32 [%0], %1;"
                     :: "l"(cnt), "r"(1u) : "memory");
        unsigned v;
        do {
            asm volatile("ld.acquire.gpu.global.u32 %0, [%1];"
                         : "=r"(v) : "l"(cnt) : "memory");
            if (v < GROUP_CTAS) __nanosleep(64);
        } while (v < GROUP_CTAS);
    }
    __syncthreads();

    // ---- read final sums (L2-coherent), normalize in registers, store once ----
    const int mrow = m0 + wm * 32 + (lane >> 2);
    const int ncol_l = wn * 32 + 2 * (lane & 3);
    float rs[8];
#pragma unroll
    for (int ni = 0; ni < 4; ni++) {
        rs[2 * ni]     = __fdividef(1.0f, __ldcg(&gs[ncol_l + ni * 8]));
        rs[2 * ni + 1] = __fdividef(1.0f, __ldcg(&gs[ncol_l + ni * 8 + 1]));
    }
#pragma unroll
    for (int mi = 0; mi < 2; mi++) {
#pragma unroll
        for (int ni = 0; ni < 4; ni++) {
            size_t ro = (size_t)(b * HW + mrow + mi * 16) * HW + n0 + ncol_l + ni * 8;
            __stcs((float2*)(out + ro),
                   make_float2(acc[mi][ni][0] * rs[2 * ni], acc[mi][ni][1] * rs[2 * ni + 1]));
            __stcs((float2*)(out + ro + (size_t)8 * HW),
                   make_float2(acc[mi][ni][2] * rs[2 * ni], acc[mi][ni][3] * rs[2 * ni + 1]));
        }
    }
}

extern "C" void kernel_launch(void* const* d_in, const int* in_sizes, int n_in,
                              void* d_out, int out_size) {
    const float* Mk = (const float*)d_in[0];
    const float* Qk = (const float*)d_in[1];
    float* out = (float*)d_out;

    cudaFuncSetAttribute(gemm_softmax_fused,
                         cudaFuncAttributeMaxDynamicSharedMemorySize, SMEM_BYTES);

    init_kernel<<<(BATCH * HW + 255) / 256, 256>>>();

    gemm_softmax_fused<<<BATCH * 32 * 32, 512, SMEM_BYTES>>>(Mk, Qk, out);
}